// round 4
// baseline (speedup 1.0000x reference)
#include <cuda_runtime.h>

#define NUM_USERS 50000
#define NUM_ITEMS 100000
#define NUM_NODES 150000
#define D 64
#define NNZ_E 4800000
#define BATCH_B 4096

// Static scratch (no allocation allowed anywhere — __device__ globals are the
// sanctioned mechanism; uninitialized so they live in BSS, not the cubin).
__device__ float g_bufA[(size_t)NUM_NODES * D];
__device__ float g_bufB[(size_t)NUM_NODES * D];
__device__ float g_acc [(size_t)NUM_NODES * D];
__device__ int   g_rowptr[NUM_NODES + 1];

// ---------------------------------------------------------------------------
// Kernel 1: concat user/item embeddings into bufA, init acc = all_emb.
// user_elems (3.2M floats) is divisible by 4, so a float4 never straddles
// the user/item boundary.
// ---------------------------------------------------------------------------
__global__ void init_kernel(const float* __restrict__ user_emb,
                            const float* __restrict__ item_emb) {
    int i = blockIdx.x * blockDim.x + threadIdx.x;        // float4 index
    const int total4 = NUM_NODES * D / 4;                  // 2.4M
    if (i >= total4) return;
    const int user4 = NUM_USERS * D / 4;                   // 800k
    float4 v;
    if (i < user4) {
        v = *(const float4*)(user_emb + (size_t)i * 4);
    } else {
        v = *(const float4*)(item_emb + (size_t)(i - user4) * 4);
    }
    ((float4*)g_bufA)[i] = v;
    ((float4*)g_acc)[i]  = v;
}

// ---------------------------------------------------------------------------
// Kernel 2: build CSR row pointers via binary search over sorted edge_rows
// ---------------------------------------------------------------------------
__global__ void rowptr_kernel(const int* __restrict__ edge_rows) {
    int r = blockIdx.x * blockDim.x + threadIdx.x;
    if (r > NUM_NODES) return;
    // lower_bound: first index with edge_rows[idx] >= r
    int lo = 0, hi = NNZ_E;
    while (lo < hi) {
        int mid = (lo + hi) >> 1;
        if (__ldg(edge_rows + mid) < r) lo = mid + 1;
        else hi = mid;
    }
    g_rowptr[r] = lo;
}

// ---------------------------------------------------------------------------
// Kernel 3: SpMM, one warp per row. Each lane owns 2 consecutive floats of
// the 64-wide feature row. Edges are loaded coalesced in chunks of 32 and
// broadcast lane-by-lane via shfl; per-j gather loads are independent, giving
// high MLP against L2 latency. acc += y fused into the epilogue.
//   DIR=0: x = g_bufA, y = g_bufB     DIR=1: x = g_bufB, y = g_bufA
// ---------------------------------------------------------------------------
template<int DIR>
__global__ void __launch_bounds__(256)
spmm_kernel(const int*   __restrict__ edge_cols,
            const float* __restrict__ edge_vals) {
    const float* __restrict__ x = DIR ? g_bufB : g_bufA;
    float*       __restrict__ y = DIR ? g_bufA : g_bufB;

    int gw   = (blockIdx.x * blockDim.x + threadIdx.x) >> 5;
    int lane = threadIdx.x & 31;
    if (gw >= NUM_NODES) return;

    int beg = g_rowptr[gw];
    int end = g_rowptr[gw + 1];
    const int fo = lane * 2;                 // this lane's feature offset

    float2 a = make_float2(0.f, 0.f);

    int e = beg;
    for (; e + 32 <= end; e += 32) {
        int   c = __ldg(edge_cols + e + lane);
        float v = __ldg(edge_vals + e + lane);
        #pragma unroll
        for (int j = 0; j < 32; j++) {
            int   cj = __shfl_sync(0xffffffffu, c, j);
            float vj = __shfl_sync(0xffffffffu, v, j);
            float2 xv = *(const float2*)(x + (size_t)cj * D + fo);
            a.x = fmaf(vj, xv.x, a.x);
            a.y = fmaf(vj, xv.y, a.y);
        }
    }
    int n = end - e;
    if (n > 0) {
        int   c = 0; float v = 0.f;
        if (lane < n) { c = __ldg(edge_cols + e + lane); v = __ldg(edge_vals + e + lane); }
        for (int j = 0; j < n; j++) {
            int   cj = __shfl_sync(0xffffffffu, c, j);
            float vj = __shfl_sync(0xffffffffu, v, j);
            float2 xv = *(const float2*)(x + (size_t)cj * D + fo);
            a.x = fmaf(vj, xv.x, a.x);
            a.y = fmaf(vj, xv.y, a.y);
        }
    }

    size_t o = (size_t)gw * D + fo;
    *(float2*)(y + o) = a;
    float2 ac = *(float2*)(g_acc + o);
    ac.x += a.x;
    ac.y += a.y;
    *(float2*)(g_acc + o) = ac;
}

// ---------------------------------------------------------------------------
// Kernel 4: batched dot products. One warp per batch element.
// gamma = dot(acc_u, acc_i) / 16   (folds /(N_LAYERS+1)=/4 on each operand)
// ---------------------------------------------------------------------------
__global__ void __launch_bounds__(256)
dot_kernel(const int* __restrict__ users,
           const int* __restrict__ items,
           float* __restrict__ out) {
    int gw   = (blockIdx.x * blockDim.x + threadIdx.x) >> 5;
    int lane = threadIdx.x & 31;
    if (gw >= BATCH_B) return;

    int u  = __ldg(users + gw);
    int it = __ldg(items + gw);

    const float2* pu = (const float2*)(g_acc + (size_t)u * D);
    const float2* pi = (const float2*)(g_acc + ((size_t)(NUM_USERS + it)) * D);

    float2 a = pu[lane];
    float2 b = pi[lane];
    float s = a.x * b.x + a.y * b.y;
    #pragma unroll
    for (int o = 16; o; o >>= 1) s += __shfl_xor_sync(0xffffffffu, s, o);
    if (lane == 0) out[gw] = s * (1.0f / 16.0f);
}

// ---------------------------------------------------------------------------
// Launch — kernel launches ONLY (graph-capture safe, no runtime API calls)
// ---------------------------------------------------------------------------
extern "C" void kernel_launch(void* const* d_in, const int* in_sizes, int n_in,
                              void* d_out, int out_size) {
    const float* user_emb  = (const float*)d_in[0];
    const float* item_emb  = (const float*)d_in[1];
    const int*   edge_rows = (const int*)  d_in[2];
    const int*   edge_cols = (const int*)  d_in[3];
    const float* edge_vals = (const float*)d_in[4];
    const int*   users     = (const int*)  d_in[5];
    const int*   items     = (const int*)  d_in[6];
    float*       out       = (float*)d_out;

    // init: concat + acc
    {
        int total4 = NUM_NODES * D / 4;
        init_kernel<<<(total4 + 255) / 256, 256>>>(user_emb, item_emb);
    }
    // row pointers
    rowptr_kernel<<<(NUM_NODES + 1 + 255) / 256, 256>>>(edge_rows);
    // 3 SpMM layers, ping-pong bufA <-> bufB, acc accumulated in-place
    {
        int blk = (NUM_NODES * 32 + 255) / 256;   // 18750 blocks, 8 warps each
        spmm_kernel<0><<<blk, 256>>>(edge_cols, edge_vals);  // A -> B
        spmm_kernel<1><<<blk, 256>>>(edge_cols, edge_vals);  // B -> A
        spmm_kernel<0><<<blk, 256>>>(edge_cols, edge_vals);  // A -> B
    }
    // batched dot
    dot_kernel<<<(BATCH_B * 32 + 255) / 256, 256>>>(users, items, out);
}